// round 6
// baseline (speedup 1.0000x reference)
#include <cuda_runtime.h>
#include <cuda_bf16.h>
#include <stdint.h>
#include <math.h>

#define IN_SZ   3072
#define CORE    1024
#define OUT_N   100
#define OUT_PAD 128
#define BATCH   8192

// input dtype modes: 0=int8(packed), 1=float32, 2=int32, 3=bfloat16
__device__ int g_mode;

// ---- scratch (static device globals; no allocation) ----
__device__ __align__(16) int8_t g_WiT[CORE * IN_SZ];
__device__ __align__(16) int8_t g_WcT[CORE * CORE];
__device__ __align__(16) int8_t g_WoT[OUT_PAD * CORE];
__device__ __align__(16) int    g_bi[CORE];
__device__ __align__(16) int    g_bc[CORE];
__device__ __align__(16) int    g_bo[OUT_PAD];
__device__ __align__(16) int8_t g_in8[(size_t)BATCH * IN_SZ];
__device__ __align__(16) int8_t g_h8[(size_t)BATCH * CORE];
__device__ __align__(16) int8_t g_A2[(size_t)BATCH * CORE];
__device__ __align__(16) int8_t g_H2[(size_t)BATCH * CORE];

// ---- mode-dispatched load/store ----
__device__ __forceinline__ int ldval(const void* src, long i, int m) {
    if (m == 0) return (int)((const int8_t*)src)[i];
    if (m == 1) return (int)((const float*)src)[i];
    if (m == 2) return ((const int*)src)[i];
    return (int)__bfloat162float(((const __nv_bfloat16*)src)[i]);
}

__device__ __forceinline__ void stval(void* dst, long i, int m, int8_t r) {
    if (m == 0)      ((int8_t*)dst)[i] = r;
    else if (m == 1) ((float*)dst)[i] = (float)r;
    else if (m == 2) ((int*)dst)[i] = (int)r;
    else             ((__nv_bfloat16*)dst)[i] = __float2bfloat16((float)r);
}

// ---- input dtype detection (constrained by unit = bytes/reported-size) ----
__global__ void detect_mode(const void* w, int unit) {
    if (unit == 2) { g_mode = 3; return; }
    const unsigned* p = (const unsigned*)w;
    bool okI = true, okF = true, okB = true;
    for (int i = 0; i < 256; i++) {
        unsigned r = p[i * 101];
        int vi = (int)r;
        if (vi < -10 || vi > 10) okI = false;
        float f = __int_as_float(r);
        if (!(isfinite(f) && f == truncf(f) && fabsf(f) <= 10.0f &&
              (f == 0.0f || fabsf(f) >= 1.0f))) okF = false;
        for (int h = 0; h < 2; h++) {
            unsigned half = (h == 0) ? (r & 0xFFFFu) : (r >> 16);
            float fb = __int_as_float(half << 16);
            if (!(isfinite(fb) && fb == truncf(fb) && fabsf(fb) <= 10.0f &&
                  (fb == 0.0f || fabsf(fb) >= 1.0f))) okB = false;
        }
    }
    if (unit == 4) { g_mode = okI ? 2 : 1; return; }
    g_mode = okI ? 2 : (okF ? 1 : (okB ? 3 : 0));
}

__global__ void conv_act(const void* __restrict__ src, int8_t* __restrict__ dst, int count) {
    int i = blockIdx.x * blockDim.x + threadIdx.x;
    if (i >= count) return;
    dst[i] = (int8_t)ldval(src, i, g_mode);
}

// W,E: [Kdim, Ncols]; dst: [Npad, Kdim]
__global__ void prep_w(const void* __restrict__ W, const void* __restrict__ E,
                       int8_t* __restrict__ dst, int Kdim, int Ncols, int Npad) {
    int tid = blockIdx.x * blockDim.x + threadIdx.x;
    if (tid >= Npad * Kdim) return;
    int n = tid / Kdim, k = tid % Kdim;
    int8_t v = 0;
    if (n < Ncols) {
        long idx = (long)k * Ncols + n;
        v = (int8_t)(ldval(W, idx, g_mode) + ldval(E, idx, g_mode));
    }
    dst[tid] = v;
}

__global__ void prep_bias(const void* bi, const void* ebi,
                          const void* bc, const void* ebc,
                          const void* bo, const void* ebo) {
    int t = blockIdx.x * blockDim.x + threadIdx.x;
    int m = g_mode;
    if (t < CORE) {
        g_bi[t] = (int)(int8_t)(ldval(bi, t, m) + ldval(ebi, t, m));
    } else if (t < 2 * CORE) {
        int i = t - CORE;
        g_bc[i] = (int)(int8_t)(ldval(bc, i, m) + ldval(ebc, i, m));
    } else if (t < 2 * CORE + OUT_PAD) {
        int i = t - 2 * CORE;
        g_bo[i] = (i < OUT_N) ? (int)(int8_t)(ldval(bo, i, m) + ldval(ebo, i, m)) : 0;
    }
}

// ---------------- tiled int8 GEMM (dp4a) ----------------
// LAYER 1: A2 = int8(int8(acc+bias) + H)       (int8 scratch)
// LAYER 2: r -> g_H2 (int8) AND d_out[m*CORE+n] (mode_out dtype)
// LAYER 3: r -> d_out[BATCH*CORE + m*100+n]     (mode_out dtype)
template <int LAYER>
__global__ void __launch_bounds__(256)
gemm_i8(const int8_t* __restrict__ A, const int8_t* __restrict__ Bt,
        const int* __restrict__ bias, int8_t* __restrict__ Cs,
        void* __restrict__ Dout, const int8_t* __restrict__ H, int K,
        int mode_out, long out_elems) {
    __shared__ __align__(16) int As[16][64];
    __shared__ __align__(16) int Bs[16][64];

    const int tid  = threadIdx.x;
    const int lrow = tid >> 2;
    const int lseg = tid & 3;
    const int ty   = tid >> 4;
    const int tx   = tid & 15;

    const int m_tile = blockIdx.y * 64;
    const int n_tile = blockIdx.x * 64;

    const int8_t* Aptr = A + (size_t)(m_tile + lrow) * K + lseg * 16;
    const int8_t* Bptr = Bt + (size_t)(n_tile + lrow) * K + lseg * 16;

    int acc[4][4];
#pragma unroll
    for (int i = 0; i < 4; i++)
#pragma unroll
        for (int j = 0; j < 4; j++) acc[i][j] = 0;

    for (int k0 = 0; k0 < K; k0 += 64) {
        int4 av = *(const int4*)(Aptr + k0);
        int4 bv = *(const int4*)(Bptr + k0);

        __syncthreads();
        As[lseg * 4 + 0][lrow] = av.x;
        As[lseg * 4 + 1][lrow] = av.y;
        As[lseg * 4 + 2][lrow] = av.z;
        As[lseg * 4 + 3][lrow] = av.w;
        Bs[lseg * 4 + 0][lrow] = bv.x;
        Bs[lseg * 4 + 1][lrow] = bv.y;
        Bs[lseg * 4 + 2][lrow] = bv.z;
        Bs[lseg * 4 + 3][lrow] = bv.w;
        __syncthreads();

#pragma unroll
        for (int kk = 0; kk < 16; kk++) {
            int4 a = *(const int4*)&As[kk][ty * 4];
            int4 b = *(const int4*)&Bs[kk][tx * 4];
            acc[0][0] = __dp4a(a.x, b.x, acc[0][0]);
            acc[0][1] = __dp4a(a.x, b.y, acc[0][1]);
            acc[0][2] = __dp4a(a.x, b.z, acc[0][2]);
            acc[0][3] = __dp4a(a.x, b.w, acc[0][3]);
            acc[1][0] = __dp4a(a.y, b.x, acc[1][0]);
            acc[1][1] = __dp4a(a.y, b.y, acc[1][1]);
            acc[1][2] = __dp4a(a.y, b.z, acc[1][2]);
            acc[1][3] = __dp4a(a.y, b.w, acc[1][3]);
            acc[2][0] = __dp4a(a.z, b.x, acc[2][0]);
            acc[2][1] = __dp4a(a.z, b.y, acc[2][1]);
            acc[2][2] = __dp4a(a.z, b.z, acc[2][2]);
            acc[2][3] = __dp4a(a.z, b.w, acc[2][3]);
            acc[3][0] = __dp4a(a.w, b.x, acc[3][0]);
            acc[3][1] = __dp4a(a.w, b.y, acc[3][1]);
            acc[3][2] = __dp4a(a.w, b.z, acc[3][2]);
            acc[3][3] = __dp4a(a.w, b.w, acc[3][3]);
        }
    }

#pragma unroll
    for (int i = 0; i < 4; i++) {
        int m = m_tile + ty * 4 + i;
#pragma unroll
        for (int j = 0; j < 4; j++) {
            int n = n_tile + tx * 4 + j;
            int8_t r = (int8_t)(acc[i][j] + bias[n]);  // truncation == mod 256
            if (LAYER == 1) {
                r = (int8_t)(r + H[(size_t)m * CORE + n]);
                Cs[(size_t)m * CORE + n] = r;
            } else if (LAYER == 2) {
                Cs[(size_t)m * CORE + n] = r;
                long oi = (long)m * CORE + n;
                if (oi < out_elems) stval(Dout, oi, mode_out, r);
            } else {
                if (n < OUT_N) {
                    long oi = (long)BATCH * CORE + (long)m * OUT_N + n;
                    if (oi < out_elems) stval(Dout, oi, mode_out, r);
                }
            }
        }
    }
}

extern "C" void kernel_launch(void* const* d_in, const int* in_sizes, int n_in,
                              void* d_out, int out_size) {
    // ---- rank-based classification (invariant to bytes-vs-elements sizing) ----
    int idx[64];
    int cnt = (n_in < 64) ? n_in : 64;
    for (int i = 0; i < cnt; i++) idx[i] = i;
    for (int a = 1; a < cnt; a++) {
        int t = idx[a], b = a - 1;
        while (b >= 0 && in_sizes[idx[b]] < in_sizes[t]) { idx[b + 1] = idx[b]; b--; }
        idx[b + 1] = t;
    }

    const void *inputs = 0, *hiddens = 0, *Wi = 0, *ei = 0, *Wc = 0, *ec = 0;
    const void *Wo = 0, *eo = 0, *bo = 0, *ebo = 0;
    const void *bi = 0, *bc = 0, *ebi = 0, *ebc = 0;
    long unit = 1;

    if (cnt >= 14) {
        inputs  = d_in[idx[0]];
        hiddens = d_in[idx[1]];
        Wi = d_in[idx[2]];  ei = d_in[idx[3]];   // W/e swap harmless (summed)
        Wc = d_in[idx[4]];  ec = d_in[idx[5]];
        Wo = d_in[idx[6]];  eo = d_in[idx[7]];
        bo = d_in[idx[12]]; ebo = d_in[idx[13]];
        bool alpha = (idx[4] < idx[2]);  // Wc before Wi -> alphabetical ordering
        if (alpha) { bc = d_in[idx[8]]; bi = d_in[idx[9]]; ebc = d_in[idx[10]]; ebi = d_in[idx[11]]; }
        else       { bi = d_in[idx[8]]; bc = d_in[idx[9]]; ebi = d_in[idx[10]]; ebc = d_in[idx[11]]; }
        unit = (long)in_sizes[idx[0]] / ((long)BATCH * IN_SZ);
        if (unit < 1) unit = 1;
    } else {
        Wi = d_in[0];  bi = d_in[1];  Wc = d_in[2];  bc = d_in[3];
        Wo = d_in[4];  bo = d_in[5];  ei = d_in[6];  ebi = d_in[7];
        ec = d_in[8];  ebc = d_in[9]; eo = d_in[10]; ebo = d_in[11];
        inputs = d_in[12]; hiddens = d_in[13];
    }

    // ---- OUTPUT dtype is independent of input dtype (key fix this round) ----
    // Reference outputs are int8, but the harness dtype set is {f32,i32,bf16};
    // NaN-in-comparison evidence from R1-R5 => output buffer is float-typed.
    const long total_out = (long)BATCH * CORE + (long)BATCH * OUT_N;  // 9207808
    int mode_out = 1;                                  // float32 default
    if ((long)out_size == 2 * total_out) mode_out = 3; // bytes-reported bf16
    long out_elems = total_out;

    void *pWiT, *pWcT, *pWoT, *pbi, *pbc, *pbo, *pin8, *ph8, *pA2, *pH2;
    cudaGetSymbolAddress(&pWiT, g_WiT);
    cudaGetSymbolAddress(&pWcT, g_WcT);
    cudaGetSymbolAddress(&pWoT, g_WoT);
    cudaGetSymbolAddress(&pbi, g_bi);
    cudaGetSymbolAddress(&pbc, g_bc);
    cudaGetSymbolAddress(&pbo, g_bo);
    cudaGetSymbolAddress(&pin8, g_in8);
    cudaGetSymbolAddress(&ph8, g_h8);
    cudaGetSymbolAddress(&pA2, g_A2);
    cudaGetSymbolAddress(&pH2, g_H2);

    detect_mode<<<1, 1>>>(Wi, (int)unit);

    conv_act<<<(BATCH * IN_SZ + 255) / 256, 256>>>(inputs, (int8_t*)pin8, BATCH * IN_SZ);
    conv_act<<<(BATCH * CORE + 255) / 256, 256>>>(hiddens, (int8_t*)ph8, BATCH * CORE);

    prep_w<<<(CORE * IN_SZ + 255) / 256, 256>>>(Wi, ei, (int8_t*)pWiT, IN_SZ, CORE, CORE);
    prep_w<<<(CORE * CORE + 255) / 256, 256>>>(Wc, ec, (int8_t*)pWcT, CORE, CORE, CORE);
    prep_w<<<(OUT_PAD * CORE + 255) / 256, 256>>>(Wo, eo, (int8_t*)pWoT, CORE, OUT_N, OUT_PAD);
    prep_bias<<<(2 * CORE + OUT_PAD + 255) / 256, 256>>>(bi, ebi, bc, ebc, bo, ebo);

    gemm_i8<1><<<dim3(CORE / 64, BATCH / 64), 256>>>(
        (const int8_t*)pin8, (const int8_t*)pWiT, (const int*)pbi,
        (int8_t*)pA2, nullptr, (const int8_t*)ph8, IN_SZ, mode_out, out_elems);

    gemm_i8<2><<<dim3(CORE / 64, BATCH / 64), 256>>>(
        (const int8_t*)pA2, (const int8_t*)pWcT, (const int*)pbc,
        (int8_t*)pH2, d_out, nullptr, CORE, mode_out, out_elems);

    gemm_i8<3><<<dim3(OUT_PAD / 64, BATCH / 64), 256>>>(
        (const int8_t*)pH2, (const int8_t*)pWoT, (const int*)pbo,
        nullptr, d_out, nullptr, CORE, mode_out, out_elems);
}

// round 7
// speedup vs baseline: 1.0520x; 1.0520x over previous
#include <cuda_runtime.h>
#include <cuda_bf16.h>
#include <stdint.h>
#include <math.h>

#define IN_SZ   3072
#define CORE    1024
#define OUT_N   100
#define OUT_PAD 128
#define BATCH   8192
#define LDSROW  80   // smem row stride (64B data + 16B pad) -> conflict-free LDSM

// input dtype modes: 0=int8(packed), 1=float32, 2=int32, 3=bfloat16
__device__ int g_mode;

// ---- scratch (static device globals; no allocation) ----
__device__ __align__(16) int8_t g_WiT[CORE * IN_SZ];
__device__ __align__(16) int8_t g_WcT[CORE * CORE];
__device__ __align__(16) int8_t g_WoT[OUT_PAD * CORE];
__device__ __align__(16) int    g_bi[CORE];
__device__ __align__(16) int    g_bc[CORE];
__device__ __align__(16) int    g_bo[OUT_PAD];
__device__ __align__(16) int8_t g_in8[(size_t)BATCH * IN_SZ];
__device__ __align__(16) int8_t g_h8[(size_t)BATCH * CORE];
__device__ __align__(16) int8_t g_A2[(size_t)BATCH * CORE];
__device__ __align__(16) int8_t g_H2[(size_t)BATCH * CORE];

// ---- mode-dispatched scalar load ----
__device__ __forceinline__ int ldval(const void* src, long i, int m) {
    if (m == 0) return (int)((const int8_t*)src)[i];
    if (m == 1) return (int)((const float*)src)[i];
    if (m == 2) return ((const int*)src)[i];
    return (int)__bfloat162float(((const __nv_bfloat16*)src)[i]);
}

// ---- input dtype detection (constrained by unit = bytes/reported-size) ----
__global__ void detect_mode(const void* w, int unit) {
    if (unit == 2) { g_mode = 3; return; }
    const unsigned* p = (const unsigned*)w;
    bool okI = true, okF = true, okB = true;
    for (int i = 0; i < 256; i++) {
        unsigned r = p[i * 101];
        int vi = (int)r;
        if (vi < -10 || vi > 10) okI = false;
        float f = __int_as_float(r);
        if (!(isfinite(f) && f == truncf(f) && fabsf(f) <= 10.0f &&
              (f == 0.0f || fabsf(f) >= 1.0f))) okF = false;
        for (int h = 0; h < 2; h++) {
            unsigned half = (h == 0) ? (r & 0xFFFFu) : (r >> 16);
            float fb = __int_as_float(half << 16);
            if (!(isfinite(fb) && fb == truncf(fb) && fabsf(fb) <= 10.0f &&
                  (fb == 0.0f || fabsf(fb) >= 1.0f))) okB = false;
        }
    }
    if (unit == 4) { g_mode = okI ? 2 : 1; return; }
    g_mode = okI ? 2 : (okF ? 1 : (okB ? 3 : 0));
}

// activation -> int8 (fast int4 copy when already packed int8)
__global__ void conv_act(const void* __restrict__ src, int8_t* __restrict__ dst, int count) {
    int m = g_mode;
    int i = blockIdx.x * blockDim.x + threadIdx.x;
    if (m == 0) {
        int n16 = count >> 4;
        if (i < n16) ((int4*)dst)[i] = ((const int4*)src)[i];
        return;
    }
    if (i < count) dst[i] = (int8_t)ldval(src, i, m);
}

// tiled transpose: W,E [Kdim,Ncols] -> dst [Npad,Kdim], coalesced both sides
__global__ void prep_w_t(const void* __restrict__ W, const void* __restrict__ E,
                         int8_t* __restrict__ dst, int Kdim, int Ncols) {
    __shared__ int8_t s[32][33];
    const int kb = blockIdx.x * 32, nb = blockIdx.y * 32;
    const int tx = threadIdx.x, ty = threadIdx.y;  // 32 x 8
    const int m = g_mode;
#pragma unroll
    for (int i = 0; i < 32; i += 8) {
        int k = kb + ty + i, n = nb + tx;
        int8_t v = 0;
        if (n < Ncols) {
            long idx = (long)k * Ncols + n;
            v = (int8_t)(ldval(W, idx, m) + ldval(E, idx, m));
        }
        s[ty + i][tx] = v;
    }
    __syncthreads();
#pragma unroll
    for (int i = 0; i < 32; i += 8) {
        int n = nb + ty + i, k = kb + tx;
        dst[(size_t)n * Kdim + k] = s[tx][ty + i];
    }
}

__global__ void prep_bias(const void* bi, const void* ebi,
                          const void* bc, const void* ebc,
                          const void* bo, const void* ebo) {
    int t = blockIdx.x * blockDim.x + threadIdx.x;
    int m = g_mode;
    if (t < CORE) {
        g_bi[t] = (int)(int8_t)(ldval(bi, t, m) + ldval(ebi, t, m));
    } else if (t < 2 * CORE) {
        int i = t - CORE;
        g_bc[i] = (int)(int8_t)(ldval(bc, i, m) + ldval(ebc, i, m));
    } else if (t < 2 * CORE + OUT_PAD) {
        int i = t - 2 * CORE;
        g_bo[i] = (i < OUT_N) ? (int)(int8_t)(ldval(bo, i, m) + ldval(ebo, i, m)) : 0;
    }
}

// ---------------- tensor-core int8 GEMM (mma.m16n8k32.s8) ----------------
// BM=BN=128, BK=64. 8 warps: warp grid 2(m) x 4(n), warp tile 64x32.
// A row-major [M,K] int8, Bt row-major [N,K] int8 (= B col-major). s32 acc.
// LAYER 1: Cs = int8(int8(acc+bias) + H)
// LAYER 2: Cs = int8(acc+bias); Dout[m*CORE+n] = float(r)
// LAYER 3: Dout[BATCH*CORE + m*100 + n] = float(r), n<100
template <int LAYER>
__global__ void __launch_bounds__(256, 2)
gemm_mma(const int8_t* __restrict__ A, const int8_t* __restrict__ Bt,
         const int* __restrict__ bias, int8_t* __restrict__ Cs,
         void* __restrict__ Dout, const int8_t* __restrict__ H,
         int K, int mode_out) {
    __shared__ __align__(16) int8_t sA[2][128 * LDSROW];
    __shared__ __align__(16) int8_t sB[2][128 * LDSROW];

    const int tid  = threadIdx.x;
    const int lane = tid & 31;
    const int wid  = tid >> 5;
    const int wm   = (wid & 1) * 64;   // warp m offset in tile
    const int wn   = (wid >> 1) * 32;  // warp n offset in tile
    const int m0   = blockIdx.y * 128;
    const int n0   = blockIdx.x * 128;

    // gmem tile loaders: 512 16B chunks per operand, 2 per thread
    const int row1 = tid >> 2;              // 0..63
    const int row2 = row1 + 64;
    const int seg  = (tid & 3) * 16;        // byte offset in 64B k-slab

    const int8_t* gA1 = A + (size_t)(m0 + row1) * K + seg;
    const int8_t* gA2 = A + (size_t)(m0 + row2) * K + seg;
    const int8_t* gB1 = Bt + (size_t)(n0 + row1) * K + seg;
    const int8_t* gB2 = Bt + (size_t)(n0 + row2) * K + seg;

    int acc[4][4][4];
#pragma unroll
    for (int a = 0; a < 4; a++)
#pragma unroll
        for (int b = 0; b < 4; b++)
#pragma unroll
            for (int c = 0; c < 4; c++) acc[a][b][c] = 0;

    const int nk = K >> 6;

    // preload tile 0
    {
        int4 av1 = *(const int4*)gA1;
        int4 av2 = *(const int4*)gA2;
        int4 bv1 = *(const int4*)gB1;
        int4 bv2 = *(const int4*)gB2;
        *(int4*)&sA[0][row1 * LDSROW + seg] = av1;
        *(int4*)&sA[0][row2 * LDSROW + seg] = av2;
        *(int4*)&sB[0][row1 * LDSROW + seg] = bv1;
        *(int4*)&sB[0][row2 * LDSROW + seg] = bv2;
    }
    __syncthreads();

    for (int kt = 0; kt < nk; kt++) {
        const int cur = kt & 1;
        const bool nxt = (kt + 1) < nk;
        int4 av1, av2, bv1, bv2;
        if (nxt) {
            const int off = (kt + 1) << 6;
            av1 = *(const int4*)(gA1 + off);
            av2 = *(const int4*)(gA2 + off);
            bv1 = *(const int4*)(gB1 + off);
            bv2 = *(const int4*)(gB2 + off);
        }

        const unsigned ab = (unsigned)__cvta_generic_to_shared(&sA[cur][0]);
        const unsigned bb = (unsigned)__cvta_generic_to_shared(&sB[cur][0]);

#pragma unroll
        for (int ks = 0; ks < 64; ks += 32) {
            uint32_t af[4][4];
            uint32_t bf[4][2];
            // A fragments: ldmatrix.x4 -> a0..a3 of m16n8k32
            //   lanes 0-7: rows 0-7 @k; 8-15: rows 8-15 @k; 16-23: rows 0-7 @k+16; 24-31: rows 8-15 @k+16
#pragma unroll
            for (int mf = 0; mf < 4; mf++) {
                const int r = wm + mf * 16 + (lane & 15);
                const int c = ks + ((lane >> 4) << 4);
                const unsigned p = ab + r * LDSROW + c;
                asm volatile(
                    "ldmatrix.sync.aligned.m8n8.x4.shared.b16 {%0,%1,%2,%3}, [%4];"
                    : "=r"(af[mf][0]), "=r"(af[mf][1]), "=r"(af[mf][2]), "=r"(af[mf][3])
                    : "r"(p));
            }
            // B fragments: ldmatrix.x2 -> b0,b1 (rows = n, cols = k slabs)
#pragma unroll
            for (int nf = 0; nf < 4; nf++) {
                const int r = wn + nf * 8 + (lane & 7);
                const int c = ks + (((lane >> 3) & 1) << 4);
                const unsigned p = bb + r * LDSROW + c;
                asm volatile(
                    "ldmatrix.sync.aligned.m8n8.x2.shared.b16 {%0,%1}, [%2];"
                    : "=r"(bf[nf][0]), "=r"(bf[nf][1])
                    : "r"(p));
            }
#pragma unroll
            for (int mf = 0; mf < 4; mf++)
#pragma unroll
                for (int nf = 0; nf < 4; nf++) {
                    asm volatile(
                        "mma.sync.aligned.m16n8k32.row.col.s32.s8.s8.s32 "
                        "{%0,%1,%2,%3}, {%4,%5,%6,%7}, {%8,%9}, {%0,%1,%2,%3};"
                        : "+r"(acc[mf][nf][0]), "+r"(acc[mf][nf][1]),
                          "+r"(acc[mf][nf][2]), "+r"(acc[mf][nf][3])
                        : "r"(af[mf][0]), "r"(af[mf][1]), "r"(af[mf][2]), "r"(af[mf][3]),
                          "r"(bf[nf][0]), "r"(bf[nf][1]));
                }
        }

        if (nxt) {
            __syncthreads();
            const int nb = cur ^ 1;
            *(int4*)&sA[nb][row1 * LDSROW + seg] = av1;
            *(int4*)&sA[nb][row2 * LDSROW + seg] = av2;
            *(int4*)&sB[nb][row1 * LDSROW + seg] = bv1;
            *(int4*)&sB[nb][row2 * LDSROW + seg] = bv2;
            __syncthreads();
        }
    }

    // ---- epilogue ----
    const int r  = lane >> 2;
    const int cq = (lane & 3) * 2;
#pragma unroll
    for (int mf = 0; mf < 4; mf++) {
#pragma unroll
        for (int nf = 0; nf < 4; nf++) {
#pragma unroll
            for (int half = 0; half < 2; half++) {
                const int m = m0 + wm + mf * 16 + r + half * 8;
                const int n = n0 + wn + nf * 8 + cq;
                const int v0 = acc[mf][nf][half * 2 + 0];
                const int v1 = acc[mf][nf][half * 2 + 1];
                int8_t r0 = (int8_t)(v0 + bias[n]);
                int8_t r1 = (int8_t)(v1 + bias[n + 1]);
                if (LAYER == 1) {
                    r0 = (int8_t)(r0 + H[(size_t)m * CORE + n]);
                    r1 = (int8_t)(r1 + H[(size_t)m * CORE + n + 1]);
                    Cs[(size_t)m * CORE + n]     = r0;
                    Cs[(size_t)m * CORE + n + 1] = r1;
                } else if (LAYER == 2) {
                    Cs[(size_t)m * CORE + n]     = r0;
                    Cs[(size_t)m * CORE + n + 1] = r1;
                    long oi = (long)m * CORE + n;
                    if (mode_out == 3) {
                        ((__nv_bfloat16*)Dout)[oi]     = __float2bfloat16((float)r0);
                        ((__nv_bfloat16*)Dout)[oi + 1] = __float2bfloat16((float)r1);
                    } else {
                        ((float*)Dout)[oi]     = (float)r0;
                        ((float*)Dout)[oi + 1] = (float)r1;
                    }
                } else {
                    long base = (long)BATCH * CORE + (long)m * OUT_N;
                    if (n < OUT_N) {
                        if (mode_out == 3) ((__nv_bfloat16*)Dout)[base + n] = __float2bfloat16((float)r0);
                        else               ((float*)Dout)[base + n] = (float)r0;
                    }
                    if (n + 1 < OUT_N) {
                        if (mode_out == 3) ((__nv_bfloat16*)Dout)[base + n + 1] = __float2bfloat16((float)r1);
                        else               ((float*)Dout)[base + n + 1] = (float)r1;
                    }
                }
            }
        }
    }
}

extern "C" void kernel_launch(void* const* d_in, const int* in_sizes, int n_in,
                              void* d_out, int out_size) {
    // ---- rank-based classification (proven in R6) ----
    int idx[64];
    int cnt = (n_in < 64) ? n_in : 64;
    for (int i = 0; i < cnt; i++) idx[i] = i;
    for (int a = 1; a < cnt; a++) {
        int t = idx[a], b = a - 1;
        while (b >= 0 && in_sizes[idx[b]] < in_sizes[t]) { idx[b + 1] = idx[b]; b--; }
        idx[b + 1] = t;
    }

    const void *inputs = 0, *hiddens = 0, *Wi = 0, *ei = 0, *Wc = 0, *ec = 0;
    const void *Wo = 0, *eo = 0, *bo = 0, *ebo = 0;
    const void *bi = 0, *bc = 0, *ebi = 0, *ebc = 0;
    long unit = 1;

    if (cnt >= 14) {
        inputs  = d_in[idx[0]];
        hiddens = d_in[idx[1]];
        Wi = d_in[idx[2]];  ei = d_in[idx[3]];
        Wc = d_in[idx[4]];  ec = d_in[idx[5]];
        Wo = d_in[idx[6]];  eo = d_in[idx[7]];
        bo = d_in[idx[12]]; ebo = d_in[idx[13]];
        bool alpha = (idx[4] < idx[2]);
        if (alpha) { bc = d_in[idx[8]]; bi = d_in[idx[9]]; ebc = d_in[idx[10]]; ebi = d_in[idx[11]]; }
        else       { bi = d_in[idx[8]]; bc = d_in[idx[9]]; ebi = d_in[idx[10]]; ebc = d_in[idx[11]]; }
        unit = (long)in_sizes[idx[0]] / ((long)BATCH * IN_SZ);
        if (unit < 1) unit = 1;
    } else {
        Wi = d_in[0];  bi = d_in[1];  Wc = d_in[2];  bc = d_in[3];
        Wo = d_in[4];  bo = d_in[5];  ei = d_in[6];  ebi = d_in[7];
        ec = d_in[8];  ebc = d_in[9]; eo = d_in[10]; ebo = d_in[11];
        inputs = d_in[12]; hiddens = d_in[13];
    }

    const long total_out = (long)BATCH * CORE + (long)BATCH * OUT_N;
    int mode_out = 1;                                  // float32 (proven in R6)
    if ((long)out_size == 2 * total_out) mode_out = 3; // bf16 if bytes say so

    void *pWiT, *pWcT, *pWoT, *pbi, *pbc, *pbo, *pin8, *ph8, *pA2, *pH2;
    cudaGetSymbolAddress(&pWiT, g_WiT);
    cudaGetSymbolAddress(&pWcT, g_WcT);
    cudaGetSymbolAddress(&pWoT, g_WoT);
    cudaGetSymbolAddress(&pbi, g_bi);
    cudaGetSymbolAddress(&pbc, g_bc);
    cudaGetSymbolAddress(&pbo, g_bo);
    cudaGetSymbolAddress(&pin8, g_in8);
    cudaGetSymbolAddress(&ph8, g_h8);
    cudaGetSymbolAddress(&pA2, g_A2);
    cudaGetSymbolAddress(&pH2, g_H2);

    detect_mode<<<1, 1>>>(Wi, (int)unit);

    conv_act<<<(BATCH * IN_SZ + 255) / 256, 256>>>(inputs, (int8_t*)pin8, BATCH * IN_SZ);
    conv_act<<<(BATCH * CORE + 255) / 256, 256>>>(hiddens, (int8_t*)ph8, BATCH * CORE);

    dim3 tb(32, 8);
    prep_w_t<<<dim3(IN_SZ / 32, CORE / 32), tb>>>(Wi, ei, (int8_t*)pWiT, IN_SZ, CORE);
    prep_w_t<<<dim3(CORE / 32, CORE / 32), tb>>>(Wc, ec, (int8_t*)pWcT, CORE, CORE);
    prep_w_t<<<dim3(CORE / 32, OUT_PAD / 32), tb>>>(Wo, eo, (int8_t*)pWoT, CORE, OUT_N);
    prep_bias<<<(2 * CORE + OUT_PAD + 255) / 256, 256>>>(bi, ebi, bc, ebc, bo, ebo);

    // layer 1: A2 = int8(hiddens + int8(inputs @ Wi' + bi))
    gemm_mma<1><<<dim3(CORE / 128, BATCH / 128), 256>>>(
        (const int8_t*)pin8, (const int8_t*)pWiT, (const int*)pbi,
        (int8_t*)pA2, nullptr, (const int8_t*)ph8, IN_SZ, mode_out);

    // layer 2: h2 -> d_out (float) + g_H2 (int8)
    gemm_mma<2><<<dim3(CORE / 128, BATCH / 128), 256>>>(
        (const int8_t*)pA2, (const int8_t*)pWcT, (const int*)pbc,
        (int8_t*)pH2, d_out, nullptr, CORE, mode_out);

    // layer 3: out -> d_out tail
    gemm_mma<3><<<dim3(OUT_PAD / 128, BATCH / 128), 256>>>(
        (const int8_t*)pH2, (const int8_t*)pWoT, (const int*)pbo,
        nullptr, d_out, nullptr, CORE, mode_out);
}

// round 8
// speedup vs baseline: 1.1285x; 1.0727x over previous
#include <cuda_runtime.h>
#include <cuda_bf16.h>
#include <stdint.h>
#include <math.h>

#define IN_SZ   3072
#define CORE    1024
#define OUT_N   100
#define OUT_PAD 128
#define BATCH   8192
#define LDSROW  80   // smem row stride: conflict-free LDSM

__device__ int g_mode;  // 0=int8, 1=float32, 2=int32, 3=bf16

__device__ __align__(16) int8_t g_WiT[CORE * IN_SZ];
__device__ __align__(16) int8_t g_WcT[CORE * CORE];
__device__ __align__(16) int8_t g_WoT[OUT_PAD * CORE];
__device__ __align__(16) int    g_bi[CORE];
__device__ __align__(16) int    g_bc[CORE];
__device__ __align__(16) int    g_bo[OUT_PAD];
__device__ __align__(16) int8_t g_in8[(size_t)BATCH * IN_SZ];
__device__ __align__(16) int8_t g_h8[(size_t)BATCH * CORE];
__device__ __align__(16) int8_t g_A2[(size_t)BATCH * CORE];
__device__ __align__(16) int8_t g_H2[(size_t)BATCH * CORE];

__device__ __forceinline__ int ldval(const void* src, long i, int m) {
    if (m == 0) return (int)((const int8_t*)src)[i];
    if (m == 1) return (int)((const float*)src)[i];
    if (m == 2) return ((const int*)src)[i];
    return (int)__bfloat162float(((const __nv_bfloat16*)src)[i]);
}

// parallel dtype detection: 256 threads, 1 word each, block-wide AND
__global__ void detect_mode(const void* w, int unit) {
    if (unit == 2) { if (threadIdx.x == 0) g_mode = 3; return; }
    unsigned r = ((const unsigned*)w)[threadIdx.x * 101];
    int vi = (int)r;
    bool okI = (vi >= -10 && vi <= 10);
    float f = __int_as_float(r);
    bool okF = (isfinite(f) && f == truncf(f) && fabsf(f) <= 10.0f &&
                (f == 0.0f || fabsf(f) >= 1.0f));
    bool okB = true;
    for (int h = 0; h < 2; h++) {
        unsigned half = (h == 0) ? (r & 0xFFFFu) : (r >> 16);
        float fb = __int_as_float(half << 16);
        if (!(isfinite(fb) && fb == truncf(fb) && fabsf(fb) <= 10.0f &&
              (fb == 0.0f || fabsf(fb) >= 1.0f))) okB = false;
    }
    int aI = __syncthreads_and((int)okI);
    int aF = __syncthreads_and((int)okF);
    int aB = __syncthreads_and((int)okB);
    if (threadIdx.x == 0)
        g_mode = (unit == 4) ? (aI ? 2 : 1) : (aI ? 2 : (aF ? 1 : (aB ? 3 : 0)));
}

__global__ void conv_act(const void* __restrict__ src, int8_t* __restrict__ dst, int count) {
    int m = g_mode;
    int i = blockIdx.x * blockDim.x + threadIdx.x;
    if (m == 0) {
        int n16 = count >> 4;
        if (i < n16) ((int4*)dst)[i] = ((const int4*)src)[i];
        return;
    }
    if (i < count) dst[i] = (int8_t)ldval(src, i, m);
}

__global__ void prep_w_t(const void* __restrict__ W, const void* __restrict__ E,
                         int8_t* __restrict__ dst, int Kdim, int Ncols) {
    __shared__ int8_t s[32][33];
    const int kb = blockIdx.x * 32, nb = blockIdx.y * 32;
    const int tx = threadIdx.x, ty = threadIdx.y;
    const int m = g_mode;
#pragma unroll
    for (int i = 0; i < 32; i += 8) {
        int k = kb + ty + i, n = nb + tx;
        int8_t v = 0;
        if (n < Ncols) {
            long idx = (long)k * Ncols + n;
            v = (int8_t)(ldval(W, idx, m) + ldval(E, idx, m));
        }
        s[ty + i][tx] = v;
    }
    __syncthreads();
#pragma unroll
    for (int i = 0; i < 32; i += 8) {
        int n = nb + ty + i, k = kb + tx;
        dst[(size_t)n * Kdim + k] = s[tx][ty + i];
    }
}

__global__ void prep_bias(const void* bi, const void* ebi,
                          const void* bc, const void* ebc,
                          const void* bo, const void* ebo) {
    int t = blockIdx.x * blockDim.x + threadIdx.x;
    int m = g_mode;
    if (t < CORE) {
        g_bi[t] = (int)(int8_t)(ldval(bi, t, m) + ldval(ebi, t, m));
    } else if (t < 2 * CORE) {
        int i = t - CORE;
        g_bc[i] = (int)(int8_t)(ldval(bc, i, m) + ldval(ebc, i, m));
    } else if (t < 2 * CORE + OUT_PAD) {
        int i = t - 2 * CORE;
        g_bo[i] = (i < OUT_N) ? (int)(int8_t)(ldval(bo, i, m) + ldval(ebo, i, m)) : 0;
    }
}

__device__ __forceinline__ void cpasync16(unsigned dst, const void* src) {
    asm volatile("cp.async.cg.shared.global [%0], [%1], 16;" :: "r"(dst), "l"(src));
}

// ---------------- tensor-core int8 GEMM (mma.m16n8k32.s8, cp.async) ----------------
template <int LAYER>
__global__ void __launch_bounds__(256, 2)
gemm_mma(const int8_t* __restrict__ A, const int8_t* __restrict__ Bt,
         const int* __restrict__ bias, int8_t* __restrict__ Cs,
         void* __restrict__ Dout, const int8_t* __restrict__ H,
         int K, int mode_out) {
    __shared__ __align__(16) int8_t sA[2][128 * LDSROW];
    __shared__ __align__(16) int8_t sB[2][128 * LDSROW];

    const int tid  = threadIdx.x;
    const int lane = tid & 31;
    const int wid  = tid >> 5;
    const int wm   = (wid & 1) * 64;
    const int wn   = (wid >> 1) * 32;
    const int m0   = blockIdx.y * 128;
    const int n0   = blockIdx.x * 128;

    const int row1 = tid >> 2;
    const int row2 = row1 + 64;
    const int seg  = (tid & 3) * 16;

    const int8_t* gA1 = A + (size_t)(m0 + row1) * K + seg;
    const int8_t* gA2 = A + (size_t)(m0 + row2) * K + seg;
    const int8_t* gB1 = Bt + (size_t)(n0 + row1) * K + seg;
    const int8_t* gB2 = Bt + (size_t)(n0 + row2) * K + seg;

    const unsigned uA0 = (unsigned)__cvta_generic_to_shared(&sA[0][0]);
    const unsigned uB0 = (unsigned)__cvta_generic_to_shared(&sB[0][0]);
    const unsigned dA1 = row1 * LDSROW + seg, dA2 = row2 * LDSROW + seg;

    int acc[4][4][4];
#pragma unroll
    for (int a = 0; a < 4; a++)
#pragma unroll
        for (int b = 0; b < 4; b++)
#pragma unroll
            for (int c = 0; c < 4; c++) acc[a][b][c] = 0;

    const int nk = K >> 6;
    const unsigned stageSz = 128 * LDSROW;

    // preload stage 0
    cpasync16(uA0 + dA1, gA1);
    cpasync16(uA0 + dA2, gA2);
    cpasync16(uB0 + dA1, gB1);
    cpasync16(uB0 + dA2, gB2);
    asm volatile("cp.async.commit_group;");
    asm volatile("cp.async.wait_group 0;");
    __syncthreads();

    for (int kt = 0; kt < nk; kt++) {
        const int cur = kt & 1;
        const bool nxt = (kt + 1) < nk;
        if (nxt) {
            const int off = (kt + 1) << 6;
            const unsigned sb = (cur ^ 1) * stageSz;
            cpasync16(uA0 + sb + dA1, gA1 + off);
            cpasync16(uA0 + sb + dA2, gA2 + off);
            cpasync16(uB0 + sb + dA1, gB1 + off);
            cpasync16(uB0 + sb + dA2, gB2 + off);
            asm volatile("cp.async.commit_group;");
        }

        const unsigned ab = uA0 + cur * stageSz;
        const unsigned bb = uB0 + cur * stageSz;

#pragma unroll
        for (int ks = 0; ks < 64; ks += 32) {
            uint32_t af[4][4];
            uint32_t bf[4][2];
#pragma unroll
            for (int mf = 0; mf < 4; mf++) {
                const int r = wm + mf * 16 + (lane & 15);
                const int c = ks + ((lane >> 4) << 4);
                const unsigned p = ab + r * LDSROW + c;
                asm volatile(
                    "ldmatrix.sync.aligned.m8n8.x4.shared.b16 {%0,%1,%2,%3}, [%4];"
                    : "=r"(af[mf][0]), "=r"(af[mf][1]), "=r"(af[mf][2]), "=r"(af[mf][3])
                    : "r"(p));
            }
#pragma unroll
            for (int nf = 0; nf < 4; nf++) {
                const int r = wn + nf * 8 + (lane & 7);
                const int c = ks + (((lane >> 3) & 1) << 4);
                const unsigned p = bb + r * LDSROW + c;
                asm volatile(
                    "ldmatrix.sync.aligned.m8n8.x2.shared.b16 {%0,%1}, [%2];"
                    : "=r"(bf[nf][0]), "=r"(bf[nf][1])
                    : "r"(p));
            }
#pragma unroll
            for (int mf = 0; mf < 4; mf++)
#pragma unroll
                for (int nf = 0; nf < 4; nf++) {
                    asm volatile(
                        "mma.sync.aligned.m16n8k32.row.col.s32.s8.s8.s32 "
                        "{%0,%1,%2,%3}, {%4,%5,%6,%7}, {%8,%9}, {%0,%1,%2,%3};"
                        : "+r"(acc[mf][nf][0]), "+r"(acc[mf][nf][1]),
                          "+r"(acc[mf][nf][2]), "+r"(acc[mf][nf][3])
                        : "r"(af[mf][0]), "r"(af[mf][1]), "r"(af[mf][2]), "r"(af[mf][3]),
                          "r"(bf[nf][0]), "r"(bf[nf][1]));
                }
        }

        if (nxt) {
            asm volatile("cp.async.wait_group 0;");
            __syncthreads();
        }
    }

    // ---- epilogue ----
    const int r  = lane >> 2;
    const int cq = (lane & 3) * 2;
#pragma unroll
    for (int mf = 0; mf < 4; mf++) {
#pragma unroll
        for (int nf = 0; nf < 4; nf++) {
#pragma unroll
            for (int half = 0; half < 2; half++) {
                const int m = m0 + wm + mf * 16 + r + half * 8;
                const int n = n0 + wn + nf * 8 + cq;
                const int v0 = acc[mf][nf][half * 2 + 0];
                const int v1 = acc[mf][nf][half * 2 + 1];
                int8_t r0 = (int8_t)(v0 + bias[n]);
                int8_t r1 = (int8_t)(v1 + bias[n + 1]);
                if (LAYER == 1) {
                    r0 = (int8_t)(r0 + H[(size_t)m * CORE + n]);
                    r1 = (int8_t)(r1 + H[(size_t)m * CORE + n + 1]);
                    Cs[(size_t)m * CORE + n]     = r0;
                    Cs[(size_t)m * CORE + n + 1] = r1;
                } else if (LAYER == 2) {
                    Cs[(size_t)m * CORE + n]     = r0;
                    Cs[(size_t)m * CORE + n + 1] = r1;
                    long oi = (long)m * CORE + n;
                    if (mode_out == 3) {
                        ((__nv_bfloat16*)Dout)[oi]     = __float2bfloat16((float)r0);
                        ((__nv_bfloat16*)Dout)[oi + 1] = __float2bfloat16((float)r1);
                    } else {
                        ((float*)Dout)[oi]     = (float)r0;
                        ((float*)Dout)[oi + 1] = (float)r1;
                    }
                } else {
                    long base = (long)BATCH * CORE + (long)m * OUT_N;
                    if (n < OUT_N) {
                        if (mode_out == 3) ((__nv_bfloat16*)Dout)[base + n] = __float2bfloat16((float)r0);
                        else               ((float*)Dout)[base + n] = (float)r0;
                    }
                    if (n + 1 < OUT_N) {
                        if (mode_out == 3) ((__nv_bfloat16*)Dout)[base + n + 1] = __float2bfloat16((float)r1);
                        else               ((float*)Dout)[base + n + 1] = (float)r1;
                    }
                }
            }
        }
    }
}

extern "C" void kernel_launch(void* const* d_in, const int* in_sizes, int n_in,
                              void* d_out, int out_size) {
    int idx[64];
    int cnt = (n_in < 64) ? n_in : 64;
    for (int i = 0; i < cnt; i++) idx[i] = i;
    for (int a = 1; a < cnt; a++) {
        int t = idx[a], b = a - 1;
        while (b >= 0 && in_sizes[idx[b]] < in_sizes[t]) { idx[b + 1] = idx[b]; b--; }
        idx[b + 1] = t;
    }

    const void *inputs = 0, *hiddens = 0, *Wi = 0, *ei = 0, *Wc = 0, *ec = 0;
    const void *Wo = 0, *eo = 0, *bo = 0, *ebo = 0;
    const void *bi = 0, *bc = 0, *ebi = 0, *ebc = 0;
    long unit = 1;

    if (cnt >= 14) {
        inputs  = d_in[idx[0]];
        hiddens = d_in[idx[1]];
        Wi = d_in[idx[2]];  ei = d_in[idx[3]];
        Wc = d_in[idx[4]];  ec = d_in[idx[5]];
        Wo = d_in[idx[6]];  eo = d_in[idx[7]];
        bo = d_in[idx[12]]; ebo = d_in[idx[13]];
        bool alpha = (idx[4] < idx[2]);
        if (alpha) { bc = d_in[idx[8]]; bi = d_in[idx[9]]; ebc = d_in[idx[10]]; ebi = d_in[idx[11]]; }
        else       { bi = d_in[idx[8]]; bc = d_in[idx[9]]; ebi = d_in[idx[10]]; ebc = d_in[idx[11]]; }
        unit = (long)in_sizes[idx[0]] / ((long)BATCH * IN_SZ);
        if (unit < 1) unit = 1;
    } else {
        Wi = d_in[0];  bi = d_in[1];  Wc = d_in[2];  bc = d_in[3];
        Wo = d_in[4];  bo = d_in[5];  ei = d_in[6];  ebi = d_in[7];
        ec = d_in[8];  ebc = d_in[9]; eo = d_in[10]; ebo = d_in[11];
        inputs = d_in[12]; hiddens = d_in[13];
    }

    const long total_out = (long)BATCH * CORE + (long)BATCH * OUT_N;
    int mode_out = 1;
    if ((long)out_size == 2 * total_out) mode_out = 3;

    void *pWiT, *pWcT, *pWoT, *pbi, *pbc, *pbo, *pin8, *ph8, *pA2, *pH2;
    cudaGetSymbolAddress(&pWiT, g_WiT);
    cudaGetSymbolAddress(&pWcT, g_WcT);
    cudaGetSymbolAddress(&pWoT, g_WoT);
    cudaGetSymbolAddress(&pbi, g_bi);
    cudaGetSymbolAddress(&pbc, g_bc);
    cudaGetSymbolAddress(&pbo, g_bo);
    cudaGetSymbolAddress(&pin8, g_in8);
    cudaGetSymbolAddress(&ph8, g_h8);
    cudaGetSymbolAddress(&pA2, g_A2);
    cudaGetSymbolAddress(&pH2, g_H2);

    dim3 tb(32, 8);
    // launch order arranged so gemm1 is launch index 5 (ncu -s 5 -c 1 profiles it)
    detect_mode<<<1, 256>>>(Wi, (int)unit);                                            // 0
    conv_act<<<(BATCH * IN_SZ + 255) / 256, 256>>>(inputs, (int8_t*)pin8, BATCH * IN_SZ); // 1
    conv_act<<<(BATCH * CORE + 255) / 256, 256>>>(hiddens, (int8_t*)ph8, BATCH * CORE);   // 2
    prep_bias<<<(2 * CORE + OUT_PAD + 255) / 256, 256>>>(bi, ebi, bc, ebc, bo, ebo);      // 3
    prep_w_t<<<dim3(IN_SZ / 32, CORE / 32), tb>>>(Wi, ei, (int8_t*)pWiT, IN_SZ, CORE);    // 4

    gemm_mma<1><<<dim3(CORE / 128, BATCH / 128), 256>>>(                                  // 5 <- profiled
        (const int8_t*)pin8, (const int8_t*)pWiT, (const int*)pbi,
        (int8_t*)pA2, nullptr, (const int8_t*)ph8, IN_SZ, mode_out);

    prep_w_t<<<dim3(CORE / 32, CORE / 32), tb>>>(Wc, ec, (int8_t*)pWcT, CORE, CORE);      // 6
    prep_w_t<<<dim3(CORE / 32, OUT_PAD / 32), tb>>>(Wo, eo, (int8_t*)pWoT, CORE, OUT_N);  // 7

    gemm_mma<2><<<dim3(CORE / 128, BATCH / 128), 256>>>(                                  // 8
        (const int8_t*)pA2, (const int8_t*)pWcT, (const int*)pbc,
        (int8_t*)pH2, d_out, nullptr, CORE, mode_out);

    gemm_mma<3><<<dim3(OUT_PAD / 128, BATCH / 128), 256>>>(                               // 9
        (const int8_t*)pH2, (const int8_t*)pWoT, (const int*)pbo,
        nullptr, d_out, nullptr, CORE, mode_out);
}